// round 2
// baseline (speedup 1.0000x reference)
#include <cuda_runtime.h>

#define NB 8
#define NC 16
#define NH 512
#define NW 512
#define NHW (NH * NW)
#define KCAP 16
#define MAXOVF (1 << 20)

// Per-destination-cell bins. cnt: how many sources landed in cell (b,y0,x0).
// rec: {src_pix_bits, fx, fy, unused} per slot. 512MB static scratch (allowed).
__device__ int    g_cnt[NB * NHW];
__device__ float4 g_rec[(size_t)NB * NHW * KCAP];
__device__ int    g_ovf_cnt;
__device__ float4 g_ovf[MAXOVF];

// ---------------------------------------------------------------------------
// Kernel 1: zero the counters (+ overflow counter)
// ---------------------------------------------------------------------------
__global__ void k_zero_cnt() {
    int i = blockIdx.x * blockDim.x + threadIdx.x;   // 524288 threads, int4 each
    ((int4*)g_cnt)[i] = make_int4(0, 0, 0, 0);
    if (i == 0) g_ovf_cnt = 0;
}

// ---------------------------------------------------------------------------
// Kernel 2: bin sources by destination cell (y0, x0). ONE atomic per source.
// ---------------------------------------------------------------------------
__global__ void k_bin(const float* __restrict__ flow) {
    int x = blockIdx.x * blockDim.x + threadIdx.x;
    int y = blockIdx.y;
    int b = blockIdx.z;

    int pix = (b * NH + y) * NW + x;
    float2 f = __ldg((const float2*)flow + pix);

    float xd = (float)x + f.x;
    float yd = (float)y + f.y;
    float x0f = floorf(xd), y0f = floorf(yd);
    int x0 = (int)x0f, y0 = (int)y0f;

    // Reference semantics: scatter only if ALL four corners in-bounds
    if (x0 < 0 || x0 > NW - 2 || y0 < 0 || y0 > NH - 2) return;

    float fx = xd - x0f, fy = yd - y0f;
    int cell = (b * NH + y0) * NW + x0;
    int slot = atomicAdd(&g_cnt[cell], 1);

    unsigned src_xy = (unsigned)(y * NW + x);        // pixel index within batch
    if (slot < KCAP) {
        g_rec[(size_t)cell * KCAP + slot] =
            make_float4(__uint_as_float(src_xy), fx, fy, 0.f);
    } else {
        int o = atomicAdd(&g_ovf_cnt, 1);
        if (o < MAXOVF) {
            unsigned packed = ((unsigned)b << 18) | (unsigned)(y0 * NW + x0);
            g_ovf[o] = make_float4(__uint_as_float(src_xy), fx, fy,
                                   __uint_as_float(packed));
        }
    }
}

// ---------------------------------------------------------------------------
// Kernel 3: gather. Each thread owns one dest pixel; reads its 4 neighbor
// cells' records, accumulates 16 channels in registers, writes BCHW + im1.
// No atomics, no transpose, no big scratch.
// ---------------------------------------------------------------------------
__global__ void k_gather(const float* __restrict__ im0,
                         const float* __restrict__ im1,
                         float* __restrict__ out) {
    int x = blockIdx.x * blockDim.x + threadIdx.x;
    int y = blockIdx.y;
    int b = blockIdx.z;

    float acc[NC];
#pragma unroll
    for (int c = 0; c < NC; ++c) acc[c] = 0.f;

    const float* im0b = im0 + (size_t)b * NC * NHW;

#pragma unroll
    for (int dy = 0; dy < 2; ++dy) {
        int cy = y - dy;
        if (cy < 0) continue;
#pragma unroll
        for (int dx = 0; dx < 2; ++dx) {
            int cx = x - dx;
            if (cx < 0) continue;
            int cell = (b * NH + cy) * NW + cx;
            int n = min(g_cnt[cell], KCAP);
            const float4* rp = g_rec + (size_t)cell * KCAP;
            for (int i = 0; i < n; ++i) {
                float4 r = rp[i];
                unsigned src_xy = __float_as_uint(r.x);
                float wx = dx ? r.y : 1.f - r.y;     // dx=1 -> this dest is the
                float wy = dy ? r.z : 1.f - r.z;     // east/south corner
                float w = wx * wy;
                const float* s = im0b + src_xy;
#pragma unroll
                for (int c = 0; c < NC; ++c)
                    acc[c] += w * __ldg(s + (size_t)c * NHW);
            }
        }
    }

    size_t o = (size_t)b * NC * NHW + (size_t)y * NW + x;
#pragma unroll
    for (int c = 0; c < NC; ++c)
        out[o + (size_t)c * NHW] = acc[c] + __ldg(im1 + o + (size_t)c * NHW);
}

// ---------------------------------------------------------------------------
// Kernel 4: apply rare bin-overflow sources with scalar REDs (runs after
// k_gather has written out). Expected ~0 iterations.
// ---------------------------------------------------------------------------
__global__ void k_ovf(const float* __restrict__ im0, float* __restrict__ out) {
    int total = min(g_ovf_cnt, MAXOVF);
    for (int i = blockIdx.x * blockDim.x + threadIdx.x; i < total;
         i += gridDim.x * blockDim.x) {
        float4 r = g_ovf[i];
        unsigned src_xy = __float_as_uint(r.x);
        unsigned packed = __float_as_uint(r.w);
        int b = packed >> 18;
        int cell = packed & 0x3FFFF;
        int y0 = cell / NW, x0 = cell % NW;
        float fx = r.y, fy = r.z;
        const float* s = im0 + (size_t)b * NC * NHW + src_xy;
        float* ob = out + (size_t)b * NC * NHW;
#pragma unroll
        for (int dy = 0; dy < 2; ++dy) {
#pragma unroll
            for (int dx = 0; dx < 2; ++dx) {
                float w = (dx ? fx : 1.f - fx) * (dy ? fy : 1.f - fy);
                float* op = ob + (size_t)(y0 + dy) * NW + (x0 + dx);
                for (int c = 0; c < NC; ++c)
                    atomicAdd(op + (size_t)c * NHW, w * __ldg(s + (size_t)c * NHW));
            }
        }
    }
}

// ---------------------------------------------------------------------------
extern "C" void kernel_launch(void* const* d_in, const int* in_sizes, int n_in,
                              void* d_out, int out_size) {
    const float* im0  = (const float*)d_in[0];
    const float* flow = (const float*)d_in[1];
    const float* im1  = (const float*)d_in[2];
    float* out = (float*)d_out;

    k_zero_cnt<<<2048, 256>>>();                       // 2M ints as int4
    k_bin<<<dim3(NW / 256, NH, NB), 256>>>(flow);
    k_gather<<<dim3(NW / 256, NH, NB), 256>>>(im0, im1, out);
    k_ovf<<<64, 256>>>(im0, out);
}